// round 7
// baseline (speedup 1.0000x reference)
#include <cuda_runtime.h>
#include <math.h>
#include <stdint.h>

#define V 7
#define NODE_D 48
#define OP_D 48
#define HID 96
#define GCN_D 128
#define N_LAYERS 5
#define MLP_H 200
#define NONE_OP 3

#define G 16             // graphs per CTA
#define NTHREADS 512     // 16 warps = 4 graph-groups x 4 col-groups
#define UST 66           // ull stride per node row of Y (even -> 16B alignable)

// ---- shared memory layout ----
// ull region:
#define U_Y 0
#define NU_Y (G*V*UST)              // 7392 ull
#define U_W (U_Y + NU_Y)            // 7392
#define NU_W (64*GCN_D)             // 8192 ull (k-pair-interleaved W)
#define U_F (U_W + NU_W)            // 15584 -> float region starts here
// float offsets inside float region:
#define F_G 0                        // gates 5*6*128 = 3840
#define F_S0 3840                    // 7*128 = 896
#define F_B 4736                     // 5*128 = 640
#define F_META 5376                  // 3*G*V = 336
#define F_Z 5712                     // 16*132 = 2112
#define F_TOTAL 7824
#define SMEM_BYTES (U_F*8 + F_TOTAL*4)   // 155968 B

typedef unsigned long long ull;

__device__ __forceinline__ ull pack2(float x, float y) {
    ull r; asm("mov.b64 %0, {%1, %2};" : "=l"(r) : "f"(x), "f"(y)); return r;
}
__device__ __forceinline__ void unpack2(ull v, float& x, float& y) {
    asm("mov.b64 {%0, %1}, %2;" : "=f"(x), "=f"(y) : "l"(v));
}
__device__ __forceinline__ void fma2(ull& d, ull a, ull b, ull c) {
    asm("fma.rn.f32x2 %0, %1, %2, %3;" : "=l"(d) : "l"(a), "l"(b), "l"(c));
}
__device__ __forceinline__ void add2(ull& d, ull a, ull b) {
    asm("add.rn.f32x2 %0, %1, %2;" : "=l"(d) : "l"(a), "l"(b));
}

// Precomputed, batch-independent tables
__device__ float g_s0[V*GCN_D];
__device__ float g_gate[N_LAYERS*6*GCN_D];
__device__ ull   g_Wp[(N_LAYERS-1)*64*GCN_D];   // W k-pair interleaved: [li][kp][c] = (w[2kp][c], w[2kp+1][c])

__global__ void precompute_kernel(
    const float* __restrict__ input_node_emb,
    const float* __restrict__ other_node_emb,
    const float* __restrict__ input_op_emb,
    const float* __restrict__ op_emb_table,
    const float* __restrict__ output_op_emb,
    const float* __restrict__ xh_w,
    const float* __restrict__ xh_b,
    const float* __restrict__ gcn0_w,
    const float* __restrict__ attn_w,
    const float* __restrict__ attn_b)
{
    __shared__ float y0[2][HID];
    int t = threadIdx.x;
    if (t < 2*HID) {
        int r = t / HID, c = t % HID;
        const float* e = (r == 0) ? input_node_emb : other_node_emb;
        float acc = xh_b[c];
        for (int d = 0; d < NODE_D; d++) acc += e[d] * xh_w[d*HID + c];
        y0[r][c] = acc;
    }
    __syncthreads();
    for (int idx = t; idx < V*GCN_D; idx += blockDim.x) {
        int v = idx / GCN_D, n = idx % GCN_D;
        const float* yr = y0[(v == 0) ? 0 : 1];
        float acc = 0.f;
        for (int d = 0; d < HID; d++) acc += yr[d] * gcn0_w[d*GCN_D + n];
        g_s0[idx] = acc;
    }
    for (int idx = t; idx < N_LAYERS*6*GCN_D; idx += blockDim.x) {
        int i = idx / (6*GCN_D);
        int r = idx % (6*GCN_D);
        int gi = r / GCN_D, n = r % GCN_D;
        const float* e = (gi == 0) ? input_op_emb
                       : (gi <= 4 ? op_emb_table + (gi-1)*OP_D : output_op_emb);
        float acc = attn_b[i*GCN_D + n];
        for (int d = 0; d < OP_D; d++) acc += e[d] * attn_w[(i*OP_D + d)*GCN_D + n];
        g_gate[idx] = 1.f / (1.f + expf(-acc));
    }
}

__global__ void prep_w_kernel(const float* __restrict__ gcn_w) {
    int idx = blockIdx.x * blockDim.x + threadIdx.x;
    if (idx >= (N_LAYERS-1)*64*GCN_D) return;
    int li = idx >> 13;              // /8192
    int r  = idx & 8191;
    int kp = r >> 7, c = r & 127;
    const float* wl = gcn_w + (size_t)li*GCN_D*GCN_D;
    g_Wp[idx] = pack2(wl[(2*kp)*GCN_D + c], wl[(2*kp+1)*GCN_D + c]);
}

__global__ __launch_bounds__(NTHREADS, 1) void nb101_main(
    const float* __restrict__ adjs,
    const int*   __restrict__ op_inds,
    const float* __restrict__ gcn_b,
    const float* __restrict__ mlp_w1,
    const float* __restrict__ mlp_b1,
    const float* __restrict__ mlp_w2,
    const float* __restrict__ mlp_b2,
    float* __restrict__ out,
    int Btot)
{
    extern __shared__ ull smu[];
    ull* Yp = smu + U_Y;
    ull* Wsm = smu + U_W;
    float* fbase = (float*)(smu + U_F);
    float* Gsm = fbase + F_G;
    float* S0  = fbase + F_S0;
    float* Bsm = fbase + F_B;
    int*   MMask = (int*)(fbase + F_META);
    int*   MGate = MMask + G*V;
    float* MRead = (float*)(MGate + G*V);
    float* Zsm = fbase + F_Z;

    const int t  = threadIdx.x;
    const int tx = t & 31;
    const int ty = t >> 5;            // warp id
    const int mg = ty >> 2;           // graph group (4 graphs)
    const int ng = ty & 3;            // column group (32 cols)
    const int q  = tx >> 3;           // graph within group
    const int lq = tx & 7;            // col-lane within graph
    const int gl = mg*4 + q;          // this lane's graph (0..15)
    const int c0 = ng*32 + 2*lq;      // cols owned: c0, c0+1, c0+16, c0+17
    const int gbase = blockIdx.x * G;

    // stage constant tables
    for (int i = t; i < N_LAYERS*6*GCN_D; i += NTHREADS) Gsm[i] = g_gate[i];
    for (int i = t; i < V*GCN_D;          i += NTHREADS) S0[i]  = g_s0[i];
    for (int i = t; i < N_LAYERS*GCN_D;   i += NTHREADS) Bsm[i] = gcn_b[i];

    // per-graph metadata
    if (t < G*V) {
        int g = t / V, u = t % V;
        int batch = gbase + g;
        int m = 0, gi = 0;
        float rw = 0.f;
        if (batch < Btot) {
            const float* arow = adjs + (size_t)batch*(V*V) + u*V;
            m = 1 << u;
            #pragma unroll
            for (int v2 = 0; v2 < V; v2++) if (arow[v2] != 0.f) m |= 1 << v2;
            if (u == 0)        { gi = 0; rw = 0.f; }
            else if (u == V-1) { gi = 5; rw = 1.f/6.f; }
            else {
                int op = op_inds[(size_t)batch*(V-2) + (u-1)];
                gi = 1 + op;
                rw = (op != NONE_OP) ? (1.f/6.f) : 0.f;
            }
        }
        MMask[t] = m; MGate[t] = gi; MRead[t] = rw;
    }
    __syncthreads();

    // ----- layer 0: y1 = relu(gate0*(mask-sum s0) + b0), stored as k-pair ulls -----
    for (int idx = t; idx < G*V*64; idx += NTHREADS) {
        int g  = idx / (V*64);
        int r  = idx - g*(V*64);
        int u  = r >> 6;
        int kp = r & 63;
        int n  = 2*kp;
        int m  = MMask[g*V + u];
        float s0v = 0.f, s1v = 0.f;
        #pragma unroll
        for (int v2 = 0; v2 < V; v2++) {
            if ((m >> v2) & 1) { s0v += S0[v2*GCN_D + n]; s1v += S0[v2*GCN_D + n + 1]; }
        }
        int gi = MGate[g*V + u];
        float y0v = fmaxf(Gsm[gi*GCN_D + n]     * s0v + Bsm[n],     0.f);
        float y1v = fmaxf(Gsm[gi*GCN_D + n + 1] * s1v + Bsm[n + 1], 0.f);
        Yp[(g*V + u)*UST + kp] = pack2(y0v, y1v);
    }

    // own-graph metadata in registers
    int myMask[V]; int myGate[V]; float myRead[V];
    #pragma unroll
    for (int u = 0; u < V; u++) {
        myMask[u] = MMask[gl*V + u];
        myGate[u] = MGate[gl*V + u];
        myRead[u] = MRead[gl*V + u];
    }

    // ----- layers 1..4 -----
    for (int li = 1; li < N_LAYERS; li++) {
        __syncthreads();   // previous-layer Y/W consumers done
        {   // stage this layer's k-pair-interleaved W (64KB)
            const float4* src = (const float4*)(g_Wp + (size_t)(li-1)*NU_W);
            float4* dst = (float4*)Wsm;
            for (int i = t; i < NU_W/2; i += NTHREADS) dst[i] = src[i];
        }
        __syncthreads();

        // acc[u][j]: packed (sum over even k, sum over odd k) for column j of
        // {c0, c0+1, c0+16, c0+17}
        ull acc[V][4];
        #pragma unroll
        for (int u = 0; u < V; u++)
            #pragma unroll
            for (int j = 0; j < 4; j++) acc[u][j] = 0ull;

        const ull* Yrow = Yp + gl*(V*UST);
        for (int kp = 0; kp < 64; kp += 2) {
            ulonglong2 b00 = *(const ulonglong2*)(Wsm + kp*GCN_D + c0);
            ulonglong2 b01 = *(const ulonglong2*)(Wsm + kp*GCN_D + c0 + 16);
            ulonglong2 b10 = *(const ulonglong2*)(Wsm + (kp+1)*GCN_D + c0);
            ulonglong2 b11 = *(const ulonglong2*)(Wsm + (kp+1)*GCN_D + c0 + 16);
            #pragma unroll
            for (int u = 0; u < V; u++) {
                ulonglong2 a = *(const ulonglong2*)(Yrow + u*UST + kp);
                fma2(acc[u][0], a.x, b00.x, acc[u][0]);
                fma2(acc[u][1], a.x, b00.y, acc[u][1]);
                fma2(acc[u][2], a.x, b01.x, acc[u][2]);
                fma2(acc[u][3], a.x, b01.y, acc[u][3]);
                fma2(acc[u][0], a.y, b10.x, acc[u][0]);
                fma2(acc[u][1], a.y, b10.y, acc[u][1]);
                fma2(acc[u][2], a.y, b11.x, acc[u][2]);
                fma2(acc[u][3], a.y, b11.y, acc[u][3]);
            }
        }

        __syncthreads();   // all Y reads for this layer complete before overwrite

        const bool last = (li == N_LAYERS - 1);
        const float* gbank = Gsm + li*6*GCN_D;
        const float* bbank = Bsm + li*GCN_D;
        float zacc[4] = {0.f, 0.f, 0.f, 0.f};
        #pragma unroll
        for (int u = 0; u < V; u++) {
            int m = myMask[u];
            ull s[4] = {0ull, 0ull, 0ull, 0ull};
            #pragma unroll
            for (int v2 = 0; v2 < V; v2++) {
                if ((m >> v2) & 1) {
                    add2(s[0], s[0], acc[v2][0]);
                    add2(s[1], s[1], acc[v2][1]);
                    add2(s[2], s[2], acc[v2][2]);
                    add2(s[3], s[3], acc[v2][3]);
                }
            }
            const float2 gA = *(const float2*)(gbank + myGate[u]*GCN_D + c0);
            const float2 gB = *(const float2*)(gbank + myGate[u]*GCN_D + c0 + 16);
            const float2 bA = *(const float2*)(bbank + c0);
            const float2 bB = *(const float2*)(bbank + c0 + 16);
            float y[4];
            {
                float e, o;
                unpack2(s[0], e, o); y[0] = gA.x*(e + o) + bA.x;
                unpack2(s[1], e, o); y[1] = gA.y*(e + o) + bA.y;
                unpack2(s[2], e, o); y[2] = gB.x*(e + o) + bB.x;
                unpack2(s[3], e, o); y[3] = gB.y*(e + o) + bB.y;
            }
            if (!last) {
                #pragma unroll
                for (int j = 0; j < 4; j++) y[j] = fmaxf(y[j], 0.f);
                ull* wr = Yp + (gl*V + u)*UST;
                wr[(c0 >> 1)]     = pack2(y[0], y[1]);
                wr[(c0 >> 1) + 8] = pack2(y[2], y[3]);
            } else {
                float rw = myRead[u];
                #pragma unroll
                for (int j = 0; j < 4; j++) zacc[j] += rw * y[j];
            }
        }
        if (last) {
            *(float2*)(Zsm + gl*132 + c0)      = make_float2(zacc[0], zacc[1]);
            *(float2*)(Zsm + gl*132 + c0 + 16) = make_float2(zacc[2], zacc[3]);
        }
    }
    __syncthreads();

    // ----- MLP: one warp per graph -----
    {
        const float* zrow = Zsm + ty*132;
        float accm[7];
        #pragma unroll
        for (int c = 0; c < 7; c++) accm[c] = 0.f;
        for (int k = 0; k < GCN_D; k++) {
            float zk = zrow[k];
            const float* w1p = mlp_w1 + (size_t)k*MLP_H + tx;
            #pragma unroll
            for (int c = 0; c < 7; c++) {
                int j = tx + 32*c;
                if (j < MLP_H) accm[c] = fmaf(zk, __ldg(w1p + 32*c), accm[c]);
            }
        }
        float part = 0.f;
        #pragma unroll
        for (int c = 0; c < 7; c++) {
            int j = tx + 32*c;
            if (j < MLP_H) part += fmaxf(accm[c] + mlp_b1[j], 0.f) * mlp_w2[j];
        }
        #pragma unroll
        for (int o = 16; o > 0; o >>= 1) part += __shfl_down_sync(0xffffffffu, part, o);
        if (tx == 0 && (gbase + ty) < Btot) out[gbase + ty] = part + mlp_b2[0];
    }
}

extern "C" void kernel_launch(void* const* d_in, const int* in_sizes, int n_in,
                              void* d_out, int out_size)
{
    const float* adjs           = (const float*)d_in[0];
    const int*   op_inds        = (const int*)  d_in[1];
    const float* input_node_emb = (const float*)d_in[2];
    const float* other_node_emb = (const float*)d_in[3];
    const float* input_op_emb   = (const float*)d_in[4];
    const float* op_emb_table   = (const float*)d_in[5];
    const float* output_op_emb  = (const float*)d_in[6];
    const float* xh_w           = (const float*)d_in[7];
    const float* xh_b           = (const float*)d_in[8];
    const float* gcn0_w         = (const float*)d_in[9];
    const float* gcn_w          = (const float*)d_in[10];
    const float* attn_w         = (const float*)d_in[11];
    const float* attn_b         = (const float*)d_in[12];
    const float* gcn_b          = (const float*)d_in[13];
    const float* mlp_w1         = (const float*)d_in[14];
    const float* mlp_b1         = (const float*)d_in[15];
    const float* mlp_w2         = (const float*)d_in[16];
    const float* mlp_b2         = (const float*)d_in[17];
    float* out = (float*)d_out;

    int Btot = in_sizes[0] / (V*V);

    precompute_kernel<<<1, 256>>>(input_node_emb, other_node_emb, input_op_emb,
                                  op_emb_table, output_op_emb, xh_w, xh_b,
                                  gcn0_w, attn_w, attn_b);
    prep_w_kernel<<<((N_LAYERS-1)*64*GCN_D + 511)/512, 512>>>(gcn_w);

    cudaFuncSetAttribute(nb101_main, cudaFuncAttributeMaxDynamicSharedMemorySize, SMEM_BYTES);
    int grid = (Btot + G - 1) / G;
    nb101_main<<<grid, NTHREADS, SMEM_BYTES>>>(adjs, op_inds, gcn_b,
                                               mlp_w1, mlp_b1, mlp_w2, mlp_b2, out, Btot);
}

// round 8
// speedup vs baseline: 1.2269x; 1.2269x over previous
#include <cuda_runtime.h>
#include <math.h>
#include <stdint.h>

#define V 7
#define NODE_D 48
#define OP_D 48
#define HID 96
#define GCN_D 128
#define N_LAYERS 5
#define MLP_H 200
#define NONE_OP 3

#define G 32             // graphs per CTA
#define NTHREADS 256     // 8 warps; warp = 4 graphs (quarter-warp each), 16 cols/lane
#define YST 132          // padded Y row stride (floats)

// ---- shared memory layout (float offsets) ----
#define OFF_Y 0
#define NY (G*V*YST)                    // 29568
#define OFF_W (OFF_Y + NY)              // 29568
#define NW (GCN_D*GCN_D)                // 16384
#define OFF_G (OFF_W + NW)              // 45952
#define NG (N_LAYERS*6*GCN_D)           // 3840
#define OFF_S0 (OFF_G + NG)             // 49792
#define NS0 (V*GCN_D)                   // 896
#define OFF_B (OFF_S0 + NS0)            // 50688
#define NB (N_LAYERS*GCN_D)             // 640
#define OFF_META (OFF_B + NB)           // 51328
#define NMETA (3*G*V)                   // 672
#define OFF_Z (OFF_META + NMETA)        // 52000
#define NZ (G*YST)                      // 4224
#define SMEM_FLOATS (OFF_Z + NZ)        // 56224 floats = 224896 B

typedef unsigned long long ull;

__device__ __forceinline__ ull pack2(float x, float y) {
    ull r; asm("mov.b64 %0, {%1, %2};" : "=l"(r) : "f"(x), "f"(y)); return r;
}
__device__ __forceinline__ void unpack2(ull v, float& x, float& y) {
    asm("mov.b64 {%0, %1}, %2;" : "=f"(x), "=f"(y) : "l"(v));
}
__device__ __forceinline__ void fma2(ull& d, ull a, ull b, ull c) {
    asm("fma.rn.f32x2 %0, %1, %2, %3;" : "=l"(d) : "l"(a), "l"(b), "l"(c));
}
__device__ __forceinline__ void add2(ull& d, ull a, ull b) {
    asm("add.rn.f32x2 %0, %1, %2;" : "=l"(d) : "l"(a), "l"(b));
}

// Precomputed, batch-independent tables
__device__ float g_s0[V*GCN_D];
__device__ float g_gate[N_LAYERS*6*GCN_D];

__global__ void precompute_kernel(
    const float* __restrict__ input_node_emb,
    const float* __restrict__ other_node_emb,
    const float* __restrict__ input_op_emb,
    const float* __restrict__ op_emb_table,
    const float* __restrict__ output_op_emb,
    const float* __restrict__ xh_w,
    const float* __restrict__ xh_b,
    const float* __restrict__ gcn0_w,
    const float* __restrict__ attn_w,
    const float* __restrict__ attn_b)
{
    __shared__ float y0[2][HID];
    int t = threadIdx.x;
    if (t < 2*HID) {
        int r = t / HID, c = t % HID;
        const float* e = (r == 0) ? input_node_emb : other_node_emb;
        float acc = xh_b[c];
        for (int d = 0; d < NODE_D; d++) acc += e[d] * xh_w[d*HID + c];
        y0[r][c] = acc;
    }
    __syncthreads();
    for (int idx = t; idx < V*GCN_D; idx += blockDim.x) {
        int v = idx / GCN_D, n = idx % GCN_D;
        const float* yr = y0[(v == 0) ? 0 : 1];
        float acc = 0.f;
        for (int d = 0; d < HID; d++) acc += yr[d] * gcn0_w[d*GCN_D + n];
        g_s0[idx] = acc;
    }
    for (int idx = t; idx < N_LAYERS*6*GCN_D; idx += blockDim.x) {
        int i = idx / (6*GCN_D);
        int r = idx % (6*GCN_D);
        int gi = r / GCN_D, n = r % GCN_D;
        const float* e = (gi == 0) ? input_op_emb
                       : (gi <= 4 ? op_emb_table + (gi-1)*OP_D : output_op_emb);
        float acc = attn_b[i*GCN_D + n];
        for (int d = 0; d < OP_D; d++) acc += e[d] * attn_w[(i*OP_D + d)*GCN_D + n];
        g_gate[idx] = 1.f / (1.f + expf(-acc));
    }
}

__global__ __launch_bounds__(NTHREADS, 1) void nb101_main(
    const float* __restrict__ adjs,
    const int*   __restrict__ op_inds,
    const float* __restrict__ gcn_w,
    const float* __restrict__ gcn_b,
    const float* __restrict__ mlp_w1,
    const float* __restrict__ mlp_b1,
    const float* __restrict__ mlp_w2,
    const float* __restrict__ mlp_b2,
    float* __restrict__ out,
    int Btot)
{
    extern __shared__ float sm[];
    float* Ysm = sm + OFF_Y;
    float* Wsm = sm + OFF_W;
    float* Gsm = sm + OFF_G;
    float* S0  = sm + OFF_S0;
    float* Bsm = sm + OFF_B;
    int*   MMask = (int*)(sm + OFF_META);
    int*   MGate = MMask + G*V;
    float* MRead = (float*)(MGate + G*V);
    float* Zsm = sm + OFF_Z;

    const int t  = threadIdx.x;
    const int tx = t & 31;
    const int ty = t >> 5;            // warp id (0..7)
    const int q  = tx >> 3;           // quarter-warp = graph within warp's group
    const int lq = tx & 7;            // column lane within graph
    const int gl = ty*4 + q;          // this lane's graph (0..31)
    const int c0 = lq*4;              // col groups: c0+32*i, i=0..3 (16 cols total)
    const int gbase = blockIdx.x * G;

    // stage constant tables
    for (int i = t; i < NG;  i += NTHREADS) Gsm[i] = g_gate[i];
    for (int i = t; i < NS0; i += NTHREADS) S0[i]  = g_s0[i];
    for (int i = t; i < NB;  i += NTHREADS) Bsm[i] = gcn_b[i];

    // per-graph metadata (G*V = 224 <= 256)
    if (t < G*V) {
        int g = t / V, u = t % V;
        int batch = gbase + g;
        int m = 0, gi = 0;
        float rw = 0.f;
        if (batch < Btot) {
            const float* arow = adjs + (size_t)batch*(V*V) + u*V;
            m = 1 << u;
            #pragma unroll
            for (int v2 = 0; v2 < V; v2++) if (arow[v2] != 0.f) m |= 1 << v2;
            if (u == 0)        { gi = 0; rw = 0.f; }
            else if (u == V-1) { gi = 5; rw = 1.f/6.f; }
            else {
                int op = op_inds[(size_t)batch*(V-2) + (u-1)];
                gi = 1 + op;
                rw = (op != NONE_OP) ? (1.f/6.f) : 0.f;
            }
        }
        MMask[t] = m; MGate[t] = gi; MRead[t] = rw;
    }
    __syncthreads();

    // ----- layer 0: y1 = relu(gate0 * (mask-sum of s0 rows) + b0) -----
    for (int idx = t; idx < G*V*GCN_D; idx += NTHREADS) {
        int g = idx / (V*GCN_D);
        int r = idx - g*(V*GCN_D);
        int u = r >> 7;
        int n = r & 127;
        int m = MMask[g*V + u];
        float s = 0.f;
        #pragma unroll
        for (int v2 = 0; v2 < V; v2++) s += ((m >> v2) & 1) ? S0[v2*GCN_D + n] : 0.f;
        float y = Gsm[MGate[g*V + u]*GCN_D + n] * s + Bsm[n];
        Ysm[(g*V + u)*YST + n] = fmaxf(y, 0.f);
    }

    // own-graph metadata in registers
    int myMask[V]; int myGate[V]; float myRead[V];
    #pragma unroll
    for (int u = 0; u < V; u++) {
        myMask[u] = MMask[gl*V + u];
        myGate[u] = MGate[gl*V + u];
        myRead[u] = MRead[gl*V + u];
    }

    // ----- layers 1..4: support = Y @ W; y = gate * (A_aug @ support) + b -----
    const float* yrow = Ysm + gl*(V*YST);
    for (int li = 1; li < N_LAYERS; li++) {
        __syncthreads();   // prior-layer Y/W consumers done
        {   // stage this layer's 128x128 weight (row-major, direct copy)
            const float4* wg = (const float4*)(gcn_w + (size_t)(li-1)*GCN_D*GCN_D);
            float4* ws = (float4*)Wsm;
            for (int i = t; i < NW/4; i += NTHREADS) ws[i] = wg[i];
        }
        __syncthreads();

        // acc[u][2i+h]: packed cols (c0+32i+2h, +1)
        ull acc[V][8];
        #pragma unroll
        for (int u = 0; u < V; u++)
            #pragma unroll
            for (int j = 0; j < 8; j++) acc[u][j] = 0ull;

        #pragma unroll 1
        for (int k4 = 0; k4 < GCN_D/4; k4++) {
            const int k = k4*4;
            float4 a[V];
            #pragma unroll
            for (int u = 0; u < V; u++) a[u] = *(const float4*)(yrow + u*YST + k);
            #pragma unroll
            for (int kk = 0; kk < 4; kk++) {
                const float* wr = Wsm + (k+kk)*GCN_D + c0;
                ulonglong2 b0 = *(const ulonglong2*)(wr);
                ulonglong2 b1 = *(const ulonglong2*)(wr + 32);
                ulonglong2 b2 = *(const ulonglong2*)(wr + 64);
                ulonglong2 b3 = *(const ulonglong2*)(wr + 96);
                #pragma unroll
                for (int u = 0; u < V; u++) {
                    float av = (kk == 0) ? a[u].x : (kk == 1) ? a[u].y : (kk == 2) ? a[u].z : a[u].w;
                    ull ap = pack2(av, av);
                    fma2(acc[u][0], ap, b0.x, acc[u][0]);
                    fma2(acc[u][1], ap, b0.y, acc[u][1]);
                    fma2(acc[u][2], ap, b1.x, acc[u][2]);
                    fma2(acc[u][3], ap, b1.y, acc[u][3]);
                    fma2(acc[u][4], ap, b2.x, acc[u][4]);
                    fma2(acc[u][5], ap, b2.y, acc[u][5]);
                    fma2(acc[u][6], ap, b3.x, acc[u][6]);
                    fma2(acc[u][7], ap, b3.y, acc[u][7]);
                }
            }
        }

        // aggregation + gate + bias (+relu), registers only
        const bool last = (li == N_LAYERS - 1);
        const float* gbank = Gsm + li*6*GCN_D;
        const float* bbank = Bsm + li*GCN_D;
        ull bp[8];
        #pragma unroll
        for (int i = 0; i < 4; i++) {
            ulonglong2 b2v = *(const ulonglong2*)(bbank + c0 + 32*i);
            bp[2*i] = b2v.x; bp[2*i+1] = b2v.y;
        }
        float zacc[16];
        if (last) {
            #pragma unroll
            for (int j = 0; j < 16; j++) zacc[j] = 0.f;
        }
        float yout[V][16];
        #pragma unroll
        for (int u = 0; u < V; u++) {
            int m = myMask[u];
            ull s[8];
            #pragma unroll
            for (int j = 0; j < 8; j++) s[j] = 0ull;
            #pragma unroll
            for (int v2 = 0; v2 < V; v2++) {
                if ((m >> v2) & 1) {
                    #pragma unroll
                    for (int j = 0; j < 8; j++) add2(s[j], s[j], acc[v2][j]);
                }
            }
            const float* gr = gbank + myGate[u]*GCN_D + c0;
            #pragma unroll
            for (int i = 0; i < 4; i++) {
                ulonglong2 g2 = *(const ulonglong2*)(gr + 32*i);
                ull y0p, y1p;
                fma2(y0p, g2.x, s[2*i],   bp[2*i]);
                fma2(y1p, g2.y, s[2*i+1], bp[2*i+1]);
                unpack2(y0p, yout[u][4*i],   yout[u][4*i+1]);
                unpack2(y1p, yout[u][4*i+2], yout[u][4*i+3]);
            }
            if (!last) {
                #pragma unroll
                for (int j = 0; j < 16; j++) yout[u][j] = fmaxf(yout[u][j], 0.f);
            } else {
                float rw = myRead[u];
                #pragma unroll
                for (int j = 0; j < 16; j++) zacc[j] += rw * yout[u][j];
            }
        }

        if (!last) {
            #pragma unroll
            for (int u = 0; u < V; u++) {
                float* wrw = Ysm + (gl*V + u)*YST + c0;
                #pragma unroll
                for (int i = 0; i < 4; i++)
                    *(float4*)(wrw + 32*i) = make_float4(yout[u][4*i], yout[u][4*i+1],
                                                         yout[u][4*i+2], yout[u][4*i+3]);
            }
        } else {
            float* zw = Zsm + gl*YST + c0;
            #pragma unroll
            for (int i = 0; i < 4; i++)
                *(float4*)(zw + 32*i) = make_float4(zacc[4*i], zacc[4*i+1],
                                                    zacc[4*i+2], zacc[4*i+3]);
        }
    }
    __syncthreads();

    // ----- MLP: warp ty handles graphs 4ty..4ty+3 -----
    {
        const float* z0 = Zsm + (ty*4 + 0)*YST;
        const float* z1 = Zsm + (ty*4 + 1)*YST;
        const float* z2 = Zsm + (ty*4 + 2)*YST;
        const float* z3 = Zsm + (ty*4 + 3)*YST;
        float a0[7], a1[7], a2[7], a3[7];
        #pragma unroll
        for (int c = 0; c < 7; c++) { a0[c]=0.f; a1[c]=0.f; a2[c]=0.f; a3[c]=0.f; }
        for (int k = 0; k < GCN_D; k++) {
            float zk0 = z0[k], zk1 = z1[k], zk2 = z2[k], zk3 = z3[k];
            const float* w1p = mlp_w1 + (size_t)k*MLP_H + tx;
            #pragma unroll
            for (int c = 0; c < 7; c++) {
                int j = tx + 32*c;
                if (j < MLP_H) {
                    float w = __ldg(w1p + 32*c);
                    a0[c] = fmaf(zk0, w, a0[c]);
                    a1[c] = fmaf(zk1, w, a1[c]);
                    a2[c] = fmaf(zk2, w, a2[c]);
                    a3[c] = fmaf(zk3, w, a3[c]);
                }
            }
        }
        float p0 = 0.f, p1 = 0.f, p2 = 0.f, p3 = 0.f;
        #pragma unroll
        for (int c = 0; c < 7; c++) {
            int j = tx + 32*c;
            if (j < MLP_H) {
                float b = mlp_b1[j], w2 = mlp_w2[j];
                p0 += fmaxf(a0[c] + b, 0.f) * w2;
                p1 += fmaxf(a1[c] + b, 0.f) * w2;
                p2 += fmaxf(a2[c] + b, 0.f) * w2;
                p3 += fmaxf(a3[c] + b, 0.f) * w2;
            }
        }
        #pragma unroll
        for (int o = 16; o > 0; o >>= 1) {
            p0 += __shfl_down_sync(0xffffffffu, p0, o);
            p1 += __shfl_down_sync(0xffffffffu, p1, o);
            p2 += __shfl_down_sync(0xffffffffu, p2, o);
            p3 += __shfl_down_sync(0xffffffffu, p3, o);
        }
        if (tx == 0) {
            float b2 = mlp_b2[0];
            int g0 = gbase + ty*4;
            if (g0 < Btot)     out[g0]     = p0 + b2;
            if (g0 + 1 < Btot) out[g0 + 1] = p1 + b2;
            if (g0 + 2 < Btot) out[g0 + 2] = p2 + b2;
            if (g0 + 3 < Btot) out[g0 + 3] = p3 + b2;
        }
    }
}

extern "C" void kernel_launch(void* const* d_in, const int* in_sizes, int n_in,
                              void* d_out, int out_size)
{
    const float* adjs           = (const float*)d_in[0];
    const int*   op_inds        = (const int*)  d_in[1];
    const float* input_node_emb = (const float*)d_in[2];
    const float* other_node_emb = (const float*)d_in[3];
    const float* input_op_emb   = (const float*)d_in[4];
    const float* op_emb_table   = (const float*)d_in[5];
    const float* output_op_emb  = (const float*)d_in[6];
    const float* xh_w           = (const float*)d_in[7];
    const float* xh_b           = (const float*)d_in[8];
    const float* gcn0_w         = (const float*)d_in[9];
    const float* gcn_w          = (const float*)d_in[10];
    const float* attn_w         = (const float*)d_in[11];
    const float* attn_b         = (const float*)d_in[12];
    const float* gcn_b          = (const float*)d_in[13];
    const float* mlp_w1         = (const float*)d_in[14];
    const float* mlp_b1         = (const float*)d_in[15];
    const float* mlp_w2         = (const float*)d_in[16];
    const float* mlp_b2         = (const float*)d_in[17];
    float* out = (float*)d_out;

    int Btot = in_sizes[0] / (V*V);

    precompute_kernel<<<1, 256>>>(input_node_emb, other_node_emb, input_op_emb,
                                  op_emb_table, output_op_emb, xh_w, xh_b,
                                  gcn0_w, attn_w, attn_b);

    size_t smem = SMEM_FLOATS * sizeof(float);
    cudaFuncSetAttribute(nb101_main, cudaFuncAttributeMaxDynamicSharedMemorySize, (int)smem);
    int grid = (Btot + G - 1) / G;
    nb101_main<<<grid, NTHREADS, smem>>>(adjs, op_inds, gcn_w, gcn_b,
                                         mlp_w1, mlp_b1, mlp_w2, mlp_b2, out, Btot);
}

// round 10
// speedup vs baseline: 1.4260x; 1.1623x over previous
#include <cuda_runtime.h>
#include <cuda_bf16.h>
#include <math.h>
#include <stdint.h>

#define V 7
#define NODE_D 48
#define OP_D 48
#define HID 96
#define GCN_D 128
#define N_LAYERS 5
#define MLP_H 200
#define NONE_OP 3

#define G 16             // graphs per CTA -> 112 real rows of a 128-row GEMM
#define NTHREADS 512     // 16 warps
#define YST 132          // fp32 Y stride (words)
#define PST 68           // packed bf16-pair stride (u32 words per row)

// ---- shared memory word (u32) offsets ----
#define APH 0                      // A hi pairs: 128*68
#define APL (APH + 128*PST)        // 8704
#define WPH (APL + 128*PST)        // 17408
#define WPL (WPH + 128*PST)        // 26112
#define YS  (WPL + 128*PST)        // 34816 : fp32 Y 128*132 = 16896
#define GS  (YS + 128*YST)         // 51712 : gates 5*6*128 = 3840
#define BS  (GS + N_LAYERS*6*GCN_D)// 55552 : biases 5*128 = 640
#define RMK (BS + N_LAYERS*GCN_D)  // 56192 : row masks 128
#define RGI (RMK + 128)            // 56320 : row gate idx 128
#define RRD (RGI + 128)            // 56448 : row readout w 128
#define SMEM_WORDS (RRD + 128)     // 56576 words = 226304 B

// Precomputed, batch-independent tables
__device__ float g_s0[V*GCN_D];
__device__ float g_gate[N_LAYERS*6*GCN_D];
__device__ uint32_t g_WPh[(N_LAYERS-1)*128*PST];  // W hi, fragment layout [n][kpair]
__device__ uint32_t g_WPl[(N_LAYERS-1)*128*PST];  // W lo

__device__ __forceinline__ void mma16816(float* d, const uint32_t* a, const uint32_t* b) {
    asm volatile("mma.sync.aligned.m16n8k16.row.col.f32.bf16.bf16.f32 "
        "{%0,%1,%2,%3}, {%4,%5,%6,%7}, {%8,%9}, {%0,%1,%2,%3};"
        : "+f"(d[0]), "+f"(d[1]), "+f"(d[2]), "+f"(d[3])
        : "r"(a[0]), "r"(a[1]), "r"(a[2]), "r"(a[3]), "r"(b[0]), "r"(b[1]));
}

__global__ void precompute_kernel(
    const float* __restrict__ input_node_emb,
    const float* __restrict__ other_node_emb,
    const float* __restrict__ input_op_emb,
    const float* __restrict__ op_emb_table,
    const float* __restrict__ output_op_emb,
    const float* __restrict__ xh_w,
    const float* __restrict__ xh_b,
    const float* __restrict__ gcn0_w,
    const float* __restrict__ attn_w,
    const float* __restrict__ attn_b)
{
    __shared__ float y0[2][HID];
    int t = threadIdx.x;
    if (t < 2*HID) {
        int r = t / HID, c = t % HID;
        const float* e = (r == 0) ? input_node_emb : other_node_emb;
        float acc = xh_b[c];
        for (int d = 0; d < NODE_D; d++) acc += e[d] * xh_w[d*HID + c];
        y0[r][c] = acc;
    }
    __syncthreads();
    for (int idx = t; idx < V*GCN_D; idx += blockDim.x) {
        int v = idx / GCN_D, n = idx % GCN_D;
        const float* yr = y0[(v == 0) ? 0 : 1];
        float acc = 0.f;
        for (int d = 0; d < HID; d++) acc += yr[d] * gcn0_w[d*GCN_D + n];
        g_s0[idx] = acc;
    }
    for (int idx = t; idx < N_LAYERS*6*GCN_D; idx += blockDim.x) {
        int i = idx / (6*GCN_D);
        int r = idx % (6*GCN_D);
        int gi = r / GCN_D, n = r % GCN_D;
        const float* e = (gi == 0) ? input_op_emb
                       : (gi <= 4 ? op_emb_table + (gi-1)*OP_D : output_op_emb);
        float acc = attn_b[i*GCN_D + n];
        for (int d = 0; d < OP_D; d++) acc += e[d] * attn_w[(i*OP_D + d)*GCN_D + n];
        g_gate[idx] = 1.f / (1.f + expf(-acc));
    }
}

// Pack W into mma B-fragment layout: pairs along k, rows = n, hi/lo split.
__global__ void prep_w_kernel(const float* __restrict__ gcn_w) {
    int idx = blockIdx.x * blockDim.x + threadIdx.x;
    if (idx >= (N_LAYERS-1)*GCN_D*64) return;
    int li = idx >> 13;            // /8192
    int r  = idx & 8191;
    int n  = r >> 6, kp = r & 63;
    const float* wl = gcn_w + (size_t)li*GCN_D*GCN_D;
    float w0 = wl[(2*kp)*GCN_D + n];
    float w1 = wl[(2*kp+1)*GCN_D + n];
    __nv_bfloat162 h = __floats2bfloat162_rn(w0, w1);
    __nv_bfloat162 l = __floats2bfloat162_rn(w0 - __bfloat162float(h.x),
                                             w1 - __bfloat162float(h.y));
    int o = li*128*PST + n*PST + kp;
    g_WPh[o] = *(uint32_t*)&h;
    g_WPl[o] = *(uint32_t*)&l;
}

__global__ __launch_bounds__(NTHREADS, 1) void nb101_main(
    const float* __restrict__ adjs,
    const int*   __restrict__ op_inds,
    const float* __restrict__ gcn_b,
    const float* __restrict__ mlp_w1,
    const float* __restrict__ mlp_b1,
    const float* __restrict__ mlp_w2,
    const float* __restrict__ mlp_b2,
    float* __restrict__ out,
    int Btot)
{
    extern __shared__ uint32_t smw[];
    float* smf = (float*)smw;
    int*   RMKp = (int*)(smw + RMK);
    int*   RGIp = (int*)(smw + RGI);
    float* RRDp = (float*)(smw + RRD);

    const int t  = threadIdx.x;
    const int tx = t & 31;
    const int ty = t >> 5;           // warp id 0..15
    const int gq = tx >> 2;          // mma group id (0..7)
    const int tq = tx & 3;           // mma thread-in-group
    const int mw = ty >> 2;          // warp m-tile (rows mw*32)
    const int nw = ty & 3;           // warp n-tile (cols nw*32)
    const int gbase = blockIdx.x * G;

    // stage gate/bias tables
    for (int i = t; i < N_LAYERS*6*GCN_D; i += NTHREADS) smf[GS + i] = g_gate[i];
    for (int i = t; i < N_LAYERS*GCN_D;   i += NTHREADS) smf[BS + i] = gcn_b[i];

    // per-row metadata (rows 0..111 real, 112..127 pad)
    if (t < 128) {
        int m = 0, gi = 0; float rw = 0.f;
        if (t < G*V) {
            int g = t / V, u = t - g*V;
            int batch = gbase + g;
            if (batch < Btot) {
                const float* arow = adjs + (size_t)batch*(V*V) + u*V;
                m = 1 << u;
                #pragma unroll
                for (int v2 = 0; v2 < V; v2++) if (arow[v2] != 0.f) m |= 1 << v2;
                if (u == 0)        { gi = 0; rw = 0.f; }
                else if (u == V-1) { gi = 5; rw = 1.f/6.f; }
                else {
                    int op = op_inds[(size_t)batch*(V-2) + (u-1)];
                    gi = 1 + op;
                    rw = (op != NONE_OP) ? (1.f/6.f) : 0.f;
                }
            }
        }
        RMKp[t] = m; RGIp[t] = gi; RRDp[t] = rw;
    }
    __syncthreads();

    // ----- layer 0: Y1 = relu(gate0 * (A_aug @ S0) + b0) -> Ysm fp32 -----
    {
        const int g = ty, c0 = tx*4;
        float4 sv[V];
        #pragma unroll
        for (int v = 0; v < V; v++) sv[v] = __ldg((const float4*)(g_s0 + v*GCN_D + c0));
        const float4 b4 = *(const float4*)(smf + BS + c0);
        #pragma unroll
        for (int u = 0; u < V; u++) {
            int row = g*V + u;
            int m = RMKp[row];
            float4 s = make_float4(0.f, 0.f, 0.f, 0.f);
            #pragma unroll
            for (int v = 0; v < V; v++)
                if ((m >> v) & 1) { s.x += sv[v].x; s.y += sv[v].y; s.z += sv[v].z; s.w += sv[v].w; }
            const float4 g4 = *(const float4*)(smf + GS + RGIp[row]*GCN_D + c0);
            float4 y;
            y.x = fmaxf(g4.x*s.x + b4.x, 0.f);
            y.y = fmaxf(g4.y*s.y + b4.y, 0.f);
            y.z = fmaxf(g4.z*s.z + b4.z, 0.f);
            y.w = fmaxf(g4.w*s.w + b4.w, 0.f);
            *(float4*)(smf + YS + row*YST + c0) = y;
        }
    }
    __syncthreads();

    // ----- layers 1..4 on tensor cores -----
    for (int li = 1; li < N_LAYERS; li++) {
        // AY pass: AP = A_aug @ Y (masked row sums), split bf16 hi/lo
        {
            const int g = ty, c0 = tx*4;
            float4 yv[V];
            #pragma unroll
            for (int v = 0; v < V; v++) yv[v] = *(const float4*)(smf + YS + (g*V + v)*YST + c0);
            #pragma unroll
            for (int u = 0; u < V; u++) {
                int row = g*V + u;
                int m = RMKp[row];
                float s0 = 0.f, s1 = 0.f, s2 = 0.f, s3 = 0.f;
                #pragma unroll
                for (int v = 0; v < V; v++)
                    if ((m >> v) & 1) { s0 += yv[v].x; s1 += yv[v].y; s2 += yv[v].z; s3 += yv[v].w; }
                __nv_bfloat162 hA = __floats2bfloat162_rn(s0, s1);
                __nv_bfloat162 hB = __floats2bfloat162_rn(s2, s3);
                __nv_bfloat162 lA = __floats2bfloat162_rn(s0 - __bfloat162float(hA.x),
                                                          s1 - __bfloat162float(hA.y));
                __nv_bfloat162 lB = __floats2bfloat162_rn(s2 - __bfloat162float(hB.x),
                                                          s3 - __bfloat162float(hB.y));
                uint2 hp = make_uint2(*(uint32_t*)&hA, *(uint32_t*)&hB);
                uint2 lp = make_uint2(*(uint32_t*)&lA, *(uint32_t*)&lB);
                *(uint2*)(smw + APH + row*PST + (c0 >> 1)) = hp;
                *(uint2*)(smw + APL + row*PST + (c0 >> 1)) = lp;
            }
        }
        // stage this layer's fragment-packed W
        {
            const uint4* srcH = (const uint4*)(g_WPh + (size_t)(li-1)*128*PST);
            const uint4* srcL = (const uint4*)(g_WPl + (size_t)(li-1)*128*PST);
            uint4* dstH = (uint4*)(smw + WPH);
            uint4* dstL = (uint4*)(smw + WPL);
            for (int i = t; i < 128*PST/4; i += NTHREADS) { dstH[i] = srcH[i]; dstL[i] = srcL[i]; }
        }
        __syncthreads();

        // GEMM: D(32x32 per warp) = AP @ WP, 3-pass split bf16
        float d[2][4][4];
        #pragma unroll
        for (int mt = 0; mt < 2; mt++)
            #pragma unroll
            for (int nt = 0; nt < 4; nt++)
                #pragma unroll
                for (int j = 0; j < 4; j++) d[mt][nt][j] = 0.f;

        #pragma unroll 2
        for (int kt = 0; kt < 8; kt++) {
            const int kb = kt*8 + tq;
            uint32_t ah[2][4], al[2][4], bh[4][2], bl[4][2];
            #pragma unroll
            for (int mt = 0; mt < 2; mt++) {
                int r0 = (mw*32 + mt*16 + gq)*PST + kb;
                int r1 = r0 + 8*PST;
                ah[mt][0] = smw[APH + r0];     ah[mt][1] = smw[APH + r1];
                ah[mt][2] = smw[APH + r0 + 4]; ah[mt][3] = smw[APH + r1 + 4];
                al[mt][0] = smw[APL + r0];     al[mt][1] = smw[APL + r1];
                al[mt][2] = smw[APL + r0 + 4]; al[mt][3] = smw[APL + r1 + 4];
            }
            #pragma unroll
            for (int nt = 0; nt < 4; nt++) {
                int rn = (nw*32 + nt*8 + gq)*PST + kb;
                bh[nt][0] = smw[WPH + rn]; bh[nt][1] = smw[WPH + rn + 4];
                bl[nt][0] = smw[WPL + rn]; bl[nt][1] = smw[WPL + rn + 4];
            }
            #pragma unroll
            for (int mt = 0; mt < 2; mt++)
                #pragma unroll
                for (int nt = 0; nt < 4; nt++) {
                    mma16816(d[mt][nt], ah[mt], bh[nt]);
                    mma16816(d[mt][nt], al[mt], bh[nt]);
                    mma16816(d[mt][nt], ah[mt], bl[nt]);
                }
        }

        // pointwise epilogue: y = gate*d + b (+relu), write fp32 Y
        const bool last = (li == N_LAYERS - 1);
        #pragma unroll
        for (int mt = 0; mt < 2; mt++) {
            #pragma unroll
            for (int nt = 0; nt < 4; nt++) {
                int R = mw*32 + mt*16 + gq;
                int C = nw*32 + nt*8 + 2*tq;
                float2 g0 = *(const float2*)(smf + GS + li*6*GCN_D + RGIp[R]*GCN_D + C);
                float2 g1 = *(const float2*)(smf + GS + li*6*GCN_D + RGIp[R+8]*GCN_D + C);
                float2 bb = *(const float2*)(smf + BS + li*GCN_D + C);
                float y0 = g0.x*d[mt][nt][0] + bb.x;
                float y1 = g0.y*d[mt][nt][1] + bb.y;
                float y2 = g1.x*d[mt][nt][2] + bb.x;
                float y3 = g1.y*d[mt][nt][3] + bb.y;
                if (!last) {
                    y0 = fmaxf(y0, 0.f); y1 = fmaxf(y1, 0.f);
                    y2 = fmaxf(y2, 0.f); y3 = fmaxf(y3, 0.f);
                }
                *(float2*)(smf + YS + R*YST + C)     = make_float2(y0, y1);
                *(float2*)(smf + YS + (R+8)*YST + C) = make_float2(y2, y3);
            }
        }
        __syncthreads();
    }

    // ----- readout: z[g] = sum_u rw[u] * Y[g*7+u]; store to pad rows 112+g -----
    {
        const int g = ty, c0 = tx*4;
        float4 z = make_float4(0.f, 0.f, 0.f, 0.f);
        #pragma unroll
        for (int u = 0; u < V; u++) {
            int row = g*V + u;
            float rw = RRDp[row];
            float4 yv = *(const float4*)(smf + YS + row*YST + c0);
            z.x += rw*yv.x; z.y += rw*yv.y; z.z += rw*yv.z; z.w += rw*yv.w;
        }
        *(float4*)(smf + YS + (112 + g)*YST + c0) = z;
    }
    __syncthreads();

    // ----- MLP: one warp per graph -----
    {
        const float* zrow = smf + YS + (112 + ty)*YST;
        float accm[7];
        #pragma unroll
        for (int c = 0; c < 7; c++) accm[c] = 0.f;
        for (int k = 0; k < GCN_D; k++) {
            float zk = zrow[k];
            const float* w1p = mlp_w1 + (size_t)k*MLP_H + tx;
            #pragma unroll
            for (int c = 0; c < 7; c++) {
                int j = tx + 32*c;
                if (j < MLP_H) accm[c] = fmaf(zk, __ldg(w1p + 32*c), accm[c]);
            }
        }
        float part = 0.f;
        #pragma unroll
        for (int c = 0; c < 7; c++) {
            int j = tx + 32*c;
            if (j < MLP_H) part += fmaxf(accm[c] + mlp_b1[j], 0.f) * mlp_w2[j];
        }
        #pragma unroll
        for (int o = 16; o > 0; o >>= 1) part += __shfl_down_sync(0xffffffffu, part, o);
        if (tx == 0 && (gbase + ty) < Btot) out[gbase + ty] = part + mlp_b2[0];
    }
}

extern "C" void kernel_launch(void* const* d_in, const int* in_sizes, int n_in,
                              void* d_out, int out_size)
{
    const float* adjs           = (const float*)d_in[0];
    const int*   op_inds        = (const int*)  d_in[1];
    const float* input_node_emb = (const float*)d_in[2];
    const float* other_node_emb = (const float*)d_in[3];
    const float* input_op_emb   = (const float*)d_in[4];
    const float* op_emb_table   = (const float*)d_in[5];
    const float* output_op_emb  = (const float*)d_in[6];
    const float* xh_w           = (const float*)d_in[7];
    const float* xh_b           = (const float*)d_in[8];
    const float* gcn0_w         = (const float*)d_in[9];
    const float* gcn_w          = (const float*)d_in[10];
    const float* attn_w         = (const float*)d_in[11];
    const float* attn_b         = (const float*)d_in[12];
    const float* gcn_b          = (const float*)d_in[13];
    const float* mlp_w1         = (const float*)d_in[14];
    const float* mlp_b1         = (const float*)d_in[15];
    const float* mlp_w2         = (const float*)d_in[16];
    const float* mlp_b2         = (const float*)d_in[17];
    float* out = (float*)d_out;

    int Btot = in_sizes[0] / (V*V);

    precompute_kernel<<<1, 256>>>(input_node_emb, other_node_emb, input_op_emb,
                                  op_emb_table, output_op_emb, xh_w, xh_b,
                                  gcn0_w, attn_w, attn_b);
    prep_w_kernel<<<((N_LAYERS-1)*GCN_D*64 + 255)/256, 256>>>(gcn_w);

    size_t smem = SMEM_WORDS * sizeof(uint32_t);
    cudaFuncSetAttribute(nb101_main, cudaFuncAttributeMaxDynamicSharedMemorySize, (int)smem);
    int grid = (Btot + G - 1) / G;
    nb101_main<<<grid, NTHREADS, smem>>>(adjs, op_inds, gcn_b,
                                         mlp_w1, mlp_b1, mlp_w2, mlp_b2, out, Btot);
}